// round 10
// baseline (speedup 1.0000x reference)
#include <cuda_runtime.h>
#include <cuda_bf16.h>

// PeriodicConvOp == parity-scrambled 3x3 conv.
// x: [8,4,512,512] f32, weight: [32,36] f32, out: [8,8,512,512] f32.
//
// For flat channel n in [0,32): g = n>>3 (gy=g>>1, gx=g&1), o = n&7:
//   conv[n](h,w) = sum_{cin,ky,kx} W[(g*8+o)*36 + cin*9+ky*3+kx]
//                  * x[b,cin, 2h+gy+ky-1, 2w+gx+kx-1]
//   out[b, n>>2, 2h + ((n>>1)&1), 2w + (n&1)] = conv[n](h,w)
//
// R10 mapping (warp-uniform weights): m = (tid>>5)&3 is PER-WARP, so every
// weight LDS.128 is a full-warp broadcast (N=1, 1 crossbar cycle instead of
// 4). Lanes: tcx = lane&3 (4 superpixels), tyl = lane>>2; ty = (tid>>7)*8
// + tyl. Tile: 16x16 superpixels (32x32 out px), 256 threads, occ 3.

#define PITCH 34   // input tile row length in (duplicated) float2 elements

__device__ __forceinline__ void ffma2(unsigned long long& d,
                                      unsigned long long a,
                                      unsigned long long b) {
    asm("fma.rn.f32x2 %0, %1, %2, %0;" : "+l"(d) : "l"(a), "l"(b));
}

// load 10 consecutive packed {v,v} positions (5x LDS.128)
__device__ __forceinline__ void ldrow(unsigned long long* r, const float2* p) {
    const ulonglong2 a = *(const ulonglong2*)(p);
    const ulonglong2 b = *(const ulonglong2*)(p + 2);
    const ulonglong2 c = *(const ulonglong2*)(p + 4);
    const ulonglong2 d = *(const ulonglong2*)(p + 6);
    const ulonglong2 e = *(const ulonglong2*)(p + 8);
    r[0] = a.x; r[1] = a.y; r[2] = b.x; r[3] = b.y; r[4] = c.x;
    r[5] = c.y; r[6] = d.x; r[7] = d.y; r[8] = e.x; r[9] = e.y;
}

__global__ __launch_bounds__(256, 3)
void pconv_kernel(const float* __restrict__ x, const float* __restrict__ wg,
                  float* __restrict__ out) {
    // input tile, each element duplicated {v,v} for packed-broadcast LDS.128
    __shared__ __align__(16) float2 s_in[4 * 34 * PITCH];
    // weights: s_w[((tap*4 + m)*4 + g)*2 + e] = W[(g*8 + 2m + e)*36 + tap]
    __shared__ __align__(16) float s_w[1152];

    const int tid  = threadIdx.x;
    const int lane = tid & 31;
    const int wid8 = tid >> 5;            // warp id 0..7
    const int b   = blockIdx.z;
    const int h0  = blockIdx.y * 16;      // superpixel row base
    const int w0  = blockIdx.x * 16;      // superpixel col base
    const int py0 = 2 * h0 - 1;           // pixel row of tile row 0
    const int px0 = 2 * w0 - 1;

    // ---- stage weights (transposed/interleaved) ----
    for (int d = tid; d < 1152; d += 256) {
        int e = d & 1, g = (d >> 1) & 3, m = (d >> 3) & 3, tap = d >> 5;
        s_w[d] = wg[(g * 8 + 2 * m + e) * 36 + tap];
    }

    // ---- stage input tile (duplicated), warp-per-row, division-free ----
    const float* xb = x + (size_t)b * 4 * 512 * 512;
    #pragma unroll
    for (int cin = 0; cin < 4; cin++) {
        for (int r = wid8; r < 34; r += 8) {
            const int gr = py0 + r;
            const bool rowok = (unsigned)gr < 512u;
            const float* src = xb + ((size_t)cin * 512 + gr) * 512;
            float2* dst = &s_in[(cin * 34 + r) * PITCH];
            const int gc0 = px0 + lane;
            float v0 = 0.f;
            if (rowok && (unsigned)gc0 < 512u) v0 = src[gc0];
            dst[lane] = make_float2(v0, v0);
            if (lane < 2) {
                const int c1 = 32 + lane;
                const int gc1 = px0 + c1;
                float v1 = 0.f;
                if (rowok && (unsigned)gc1 < 512u) v1 = src[gc1];
                dst[c1] = make_float2(v1, v1);
            }
        }
    }
    __syncthreads();

    // warp-uniform m; lanes spread over pixels
    const int m   = wid8 & 3;             // PER-WARP -> uniform weight addrs
    const int tcx = lane & 3;             // 4 superpixels per thread
    const int ty  = ((tid >> 7) << 3) | (lane >> 2);   // 0..15

    const float* s_wm = s_w + m * 8;   // weight base for this warp's m

    // acc[g][sp]: f32x2 = (out j=0, out j=1) for plane co = 2g + (m>>1),
    // out row 2*(h0+ty) + (m&1), superpixel x = w0 + 4*tcx + sp
    unsigned long long acc[4][4];
    #pragma unroll
    for (int g = 0; g < 4; g++)
        #pragma unroll
        for (int sp = 0; sp < 4; sp++)
            acc[g][sp] = 0ull;

    // apply row `row` to group-half gy (g = 2*gy, 2*gy+1) at tap row ky
    #define APPLY(GY, KY, CIN, ROW)                                         \
    {                                                                       \
        _Pragma("unroll")                                                   \
        for (int kx = 0; kx < 3; kx++) {                                    \
            const float* wb = s_wm + ((CIN) * 9 + (KY) * 3 + kx) * 32       \
                              + (GY) * 4;                                   \
            const ulonglong2 wp = *(const ulonglong2*)(wb);                 \
            _Pragma("unroll")                                               \
            for (int sp = 0; sp < 4; sp++) {                                \
                ffma2(acc[2 * (GY) + 0][sp], wp.x, (ROW)[2 * sp + 0 + kx]); \
                ffma2(acc[2 * (GY) + 1][sp], wp.y, (ROW)[2 * sp + 1 + kx]); \
            }                                                               \
        }                                                                   \
    }

    #pragma unroll
    for (int cin = 0; cin < 4; cin++) {
        const float2* rowbase = &s_in[(cin * 34 + 2 * ty) * PITCH + 8 * tcx];
        unsigned long long row[10];

        ldrow(row, rowbase);                 // r = 0
        APPLY(0, 0, cin, row)                //   gy=0, ky=0
        ldrow(row, rowbase + PITCH);         // r = 1
        APPLY(0, 1, cin, row)                //   gy=0, ky=1
        APPLY(1, 0, cin, row)                //   gy=1, ky=0
        ldrow(row, rowbase + 2 * PITCH);     // r = 2
        APPLY(0, 2, cin, row)                //   gy=0, ky=2
        APPLY(1, 1, cin, row)                //   gy=1, ky=1
        ldrow(row, rowbase + 3 * PITCH);     // r = 3
        APPLY(1, 2, cin, row)                //   gy=1, ky=2
    }
    #undef APPLY

    // ---- coalesced stores: per g, 8 consecutive px = 2x STG.128 ----
    float* ob = out + (size_t)b * 8 * 512 * 512;
    const int row_y = 2 * (h0 + ty) + (m & 1);
    const int colbase = 2 * w0 + 8 * tcx;
    #pragma unroll
    for (int g = 0; g < 4; g++) {
        const int co = 2 * g + (m >> 1);
        float* orow = ob + ((size_t)co * 512 + row_y) * 512 + colbase;
        ulonglong2 v0; v0.x = acc[g][0]; v0.y = acc[g][1];
        ulonglong2 v1; v1.x = acc[g][2]; v1.y = acc[g][3];
        *(ulonglong2*)(orow) = v0;
        *(ulonglong2*)(orow + 4) = v1;
    }
}

extern "C" void kernel_launch(void* const* d_in, const int* in_sizes, int n_in,
                              void* d_out, int out_size) {
    const float* x = (const float*)d_in[0];   // [8,4,512,512]
    const float* w = (const float*)d_in[1];   // [32,36,1,1]
    float* out = (float*)d_out;               // [8,8,512,512]
    dim3 grid(16, 16, 8);                     // 2048 blocks, 256 thr
    pconv_kernel<<<grid, 256>>>(x, w, out);
}

// round 11
// speedup vs baseline: 1.3209x; 1.3209x over previous
#include <cuda_runtime.h>
#include <cuda_bf16.h>

// PeriodicConvOp == parity-scrambled 3x3 conv.
// x: [8,4,512,512] f32, weight: [32,36] f32, out: [8,8,512,512] f32.
//
// For flat channel n in [0,32): g = n>>3 (gy=g>>1, gx=g&1), o = n&7:
//   conv[n](h,w) = sum_{cin,ky,kx} W[(g*8+o)*36 + cin*9+ky*3+kx]
//                  * x[b,cin, 2h+gy+ky-1, 2w+gx+kx-1]
//   out[b, n>>2, 2h + ((n>>1)&1), 2w + (n&1)] = conv[n](h,w)
//
// R6 mapping (measured best): m = tid&3 (o-pair -> f32x2 lanes),
// tcx = (tid>>2)&3 (4 superpixels), ty = tid>>4. Tile 16x16 superpixels,
// 256 threads, occupancy 3, duplicated {v,v} input tile.
// R11: double-buffered row prefetch (loads issue 1 APPLY ahead of use) +
// predicate-free staging fast path for interior blocks.

#define PITCH 34   // input tile row length in (duplicated) float2 elements

__device__ __forceinline__ void ffma2(unsigned long long& d,
                                      unsigned long long a,
                                      unsigned long long b) {
    asm("fma.rn.f32x2 %0, %1, %2, %0;" : "+l"(d) : "l"(a), "l"(b));
}

// load 10 consecutive packed {v,v} positions (5x LDS.128)
__device__ __forceinline__ void ldrow(unsigned long long* r, const float2* p) {
    const ulonglong2 a = *(const ulonglong2*)(p);
    const ulonglong2 b = *(const ulonglong2*)(p + 2);
    const ulonglong2 c = *(const ulonglong2*)(p + 4);
    const ulonglong2 d = *(const ulonglong2*)(p + 6);
    const ulonglong2 e = *(const ulonglong2*)(p + 8);
    r[0] = a.x; r[1] = a.y; r[2] = b.x; r[3] = b.y; r[4] = c.x;
    r[5] = c.y; r[6] = d.x; r[7] = d.y; r[8] = e.x; r[9] = e.y;
}

__global__ __launch_bounds__(256, 3)
void pconv_kernel(const float* __restrict__ x, const float* __restrict__ wg,
                  float* __restrict__ out) {
    // input tile, each element duplicated {v,v} for packed-broadcast LDS.128
    __shared__ __align__(16) float2 s_in[4 * 34 * PITCH];
    // weights: s_w[((tap*4 + m)*4 + g)*2 + e] = W[(g*8 + 2m + e)*36 + tap]
    __shared__ __align__(16) float s_w[1152];

    const int tid  = threadIdx.x;
    const int lane = tid & 31;
    const int wid8 = tid >> 5;            // warp id 0..7
    const int b   = blockIdx.z;
    const int h0  = blockIdx.y * 16;      // superpixel row base
    const int w0  = blockIdx.x * 16;      // superpixel col base
    const int py0 = 2 * h0 - 1;           // pixel row of tile row 0
    const int px0 = 2 * w0 - 1;

    // ---- stage weights (transposed/interleaved) ----
    for (int d = tid; d < 1152; d += 256) {
        int e = d & 1, g = (d >> 1) & 3, m = (d >> 3) & 3, tap = d >> 5;
        s_w[d] = wg[(g * 8 + 2 * m + e) * 36 + tap];
    }

    // ---- stage input tile (duplicated), warp-per-row ----
    const float* xb = x + (size_t)b * 4 * 512 * 512;
    const bool interior = (blockIdx.x > 0) & (blockIdx.x < 15) &
                          (blockIdx.y > 0) & (blockIdx.y < 15);
    if (interior) {
        // no bounds predicates: whole 34x34 window is in-image
        #pragma unroll
        for (int cin = 0; cin < 4; cin++) {
            for (int r = wid8; r < 34; r += 8) {
                const float* src = xb + ((size_t)cin * 512 + (py0 + r)) * 512
                                   + px0;
                float2* dst = &s_in[(cin * 34 + r) * PITCH];
                const float v0 = src[lane];
                dst[lane] = make_float2(v0, v0);
                if (lane < 2) {
                    const float v1 = src[32 + lane];
                    dst[32 + lane] = make_float2(v1, v1);
                }
            }
        }
    } else {
        #pragma unroll
        for (int cin = 0; cin < 4; cin++) {
            for (int r = wid8; r < 34; r += 8) {
                const int gr = py0 + r;
                const bool rowok = (unsigned)gr < 512u;
                const float* src = xb + ((size_t)cin * 512 + gr) * 512;
                float2* dst = &s_in[(cin * 34 + r) * PITCH];
                const int gc0 = px0 + lane;
                float v0 = 0.f;
                if (rowok && (unsigned)gc0 < 512u) v0 = src[gc0];
                dst[lane] = make_float2(v0, v0);
                if (lane < 2) {
                    const int c1 = 32 + lane;
                    const int gc1 = px0 + c1;
                    float v1 = 0.f;
                    if (rowok && (unsigned)gc1 < 512u) v1 = src[gc1];
                    dst[c1] = make_float2(v1, v1);
                }
            }
        }
    }
    __syncthreads();

    const int m   = tid & 3;
    const int tcx = (tid >> 2) & 3;
    const int ty  = tid >> 4;

    const float* s_wm = s_w + m * 8;   // weight base for this thread's m

    // acc[g][sp]: f32x2 = (out j=0, out j=1) for plane co = 2g + (m>>1),
    // out row 2*(h0+ty) + (m&1), superpixel x = w0 + 4*tcx + sp
    unsigned long long acc[4][4];
    #pragma unroll
    for (int g = 0; g < 4; g++)
        #pragma unroll
        for (int sp = 0; sp < 4; sp++)
            acc[g][sp] = 0ull;

    // apply buffered row to group-half gy (g = 2*gy, 2*gy+1) at tap row ky
    #define APPLY(GY, KY, CIN, ROW)                                         \
    {                                                                       \
        _Pragma("unroll")                                                   \
        for (int kx = 0; kx < 3; kx++) {                                    \
            const float* wb = s_wm + ((CIN) * 9 + (KY) * 3 + kx) * 32       \
                              + (GY) * 4;                                   \
            const ulonglong2 wp = *(const ulonglong2*)(wb);                 \
            _Pragma("unroll")                                               \
            for (int sp = 0; sp < 4; sp++) {                                \
                ffma2(acc[2 * (GY) + 0][sp], wp.x, (ROW)[2 * sp + 0 + kx]); \
                ffma2(acc[2 * (GY) + 1][sp], wp.y, (ROW)[2 * sp + 1 + kx]); \
            }                                                               \
        }                                                                   \
    }

    #pragma unroll
    for (int cin = 0; cin < 4; cin++) {
        const float2* rowbase = &s_in[(cin * 34 + 2 * ty) * PITCH + 8 * tcx];
        unsigned long long rA[10], rB[10];

        // double-buffered schedule: each ldrow issues one APPLY ahead of use
        ldrow(rA, rowbase);                  // A = r0
        ldrow(rB, rowbase + PITCH);          // B = r1   (prefetch)
        APPLY(0, 0, cin, rA)                 // consume r0
        ldrow(rA, rowbase + 2 * PITCH);      // A = r2   (prefetch)
        APPLY(0, 1, cin, rB)                 // consume r1
        APPLY(1, 0, cin, rB)
        ldrow(rB, rowbase + 3 * PITCH);      // B = r3   (prefetch)
        APPLY(0, 2, cin, rA)                 // consume r2
        APPLY(1, 1, cin, rA)
        APPLY(1, 2, cin, rB)                 // consume r3
    }
    #undef APPLY

    // ---- coalesced stores: per g, 8 consecutive px = 2x STG.128 ----
    float* ob = out + (size_t)b * 8 * 512 * 512;
    const int row_y = 2 * (h0 + ty) + (m & 1);
    const int colbase = 2 * w0 + 8 * tcx;
    #pragma unroll
    for (int g = 0; g < 4; g++) {
        const int co = 2 * g + (m >> 1);
        float* orow = ob + ((size_t)co * 512 + row_y) * 512 + colbase;
        ulonglong2 v0; v0.x = acc[g][0]; v0.y = acc[g][1];
        ulonglong2 v1; v1.x = acc[g][2]; v1.y = acc[g][3];
        *(ulonglong2*)(orow) = v0;
        *(ulonglong2*)(orow + 4) = v1;
    }
}

extern "C" void kernel_launch(void* const* d_in, const int* in_sizes, int n_in,
                              void* d_out, int out_size) {
    const float* x = (const float*)d_in[0];   // [8,4,512,512]
    const float* w = (const float*)d_in[1];   // [32,36,1,1]
    float* out = (float*)d_out;               // [8,8,512,512]
    dim3 grid(16, 16, 8);                     // 2048 blocks, 256 thr
    pconv_kernel<<<grid, 256>>>(x, w, out);
}

// round 12
// speedup vs baseline: 1.3842x; 1.0479x over previous
#include <cuda_runtime.h>
#include <cuda_bf16.h>

// PeriodicConvOp == parity-scrambled 3x3 conv.
// x: [8,4,512,512] f32, weight: [32,36] f32, out: [8,8,512,512] f32.
//
// For flat channel n in [0,32): g = n>>3 (gy=g>>1, gx=g&1), o = n&7:
//   conv[n](h,w) = sum_{cin,ky,kx} W[(g*8+o)*36 + cin*9+ky*3+kx]
//                  * x[b,cin, 2h+gy+ky-1, 2w+gx+kx-1]
//   out[b, n>>2, 2h + ((n>>1)&1), 2w + (n&1)] = conv[n](h,w)
//
// R6/R11 thread map (measured best): m = tid&3, tcx = (tid>>2)&3,
// ty = tid>>4; 16x16-superpixel tile, 256 threads, occupancy 3,
// duplicated {v,v} input tile, double-buffered row prefetch.
//
// R12: BANK-CONFLICT-FREE input layout. Column c of a row is stored at
// float2 index 10*(c>>3) + (c&7) (2-float2 gap after each 8 positions),
// row pitch 44 float2. Warp address set per LDS.128 becomes
// {tcx*20 + tyl*16} mod 32 words = 8 distinct residues covering all 32
// banks (old layout: 2-way conflict on every input load). Instruction
// stream identical to R11; only addresses change. Input tile (47.9 KB)
// lives in dynamic smem.

#define RPITCH 44  // row pitch in float2 (8 data + 2 gap per group, x4 + tail)

__device__ __forceinline__ void ffma2(unsigned long long& d,
                                      unsigned long long a,
                                      unsigned long long b) {
    asm("fma.rn.f32x2 %0, %1, %2, %0;" : "+l"(d) : "l"(a), "l"(b));
}

// storage float2-offset of column c within a row (gapped layout)
__device__ __forceinline__ int colmap(int c) {
    return 10 * (c >> 3) + (c & 7);
}

// load 10 consecutive positions from gapped layout: base = 10*tcx float2;
// positions 0..7 at +0..+7, positions 8..9 at +10,+11.
__device__ __forceinline__ void ldrow(unsigned long long* r, const float2* p) {
    const ulonglong2 a = *(const ulonglong2*)(p);
    const ulonglong2 b = *(const ulonglong2*)(p + 2);
    const ulonglong2 c = *(const ulonglong2*)(p + 4);
    const ulonglong2 d = *(const ulonglong2*)(p + 6);
    const ulonglong2 e = *(const ulonglong2*)(p + 10);
    r[0] = a.x; r[1] = a.y; r[2] = b.x; r[3] = b.y; r[4] = c.x;
    r[5] = c.y; r[6] = d.x; r[7] = d.y; r[8] = e.x; r[9] = e.y;
}

__global__ __launch_bounds__(256, 3)
void pconv_kernel(const float* __restrict__ x, const float* __restrict__ wg,
                  float* __restrict__ out) {
    // dynamic: input tile, duplicated {v,v}, gapped conflict-free layout
    extern __shared__ __align__(16) float2 s_in[];   // 4*34*RPITCH = 47872 B
    // weights: s_w[((tap*4 + m)*4 + g)*2 + e] = W[(g*8 + 2m + e)*36 + tap]
    __shared__ __align__(16) float s_w[1152];

    const int tid  = threadIdx.x;
    const int lane = tid & 31;
    const int wid8 = tid >> 5;            // warp id 0..7
    const int b   = blockIdx.z;
    const int h0  = blockIdx.y * 16;      // superpixel row base
    const int w0  = blockIdx.x * 16;      // superpixel col base
    const int py0 = 2 * h0 - 1;           // pixel row of tile row 0
    const int px0 = 2 * w0 - 1;

    // ---- stage weights (transposed/interleaved) ----
    for (int d = tid; d < 1152; d += 256) {
        int e = d & 1, g = (d >> 1) & 3, m = (d >> 3) & 3, tap = d >> 5;
        s_w[d] = wg[(g * 8 + 2 * m + e) * 36 + tap];
    }

    // ---- stage input tile (duplicated, gapped layout), warp-per-row ----
    const float* xb = x + (size_t)b * 4 * 512 * 512;
    const int cm0 = colmap(lane);         // storage offset of column=lane
    const bool interior = (blockIdx.x > 0) & (blockIdx.x < 15) &
                          (blockIdx.y > 0) & (blockIdx.y < 15);
    if (interior) {
        #pragma unroll
        for (int cin = 0; cin < 4; cin++) {
            for (int r = wid8; r < 34; r += 8) {
                const float* src = xb + ((size_t)cin * 512 + (py0 + r)) * 512
                                   + px0;
                float2* dst = &s_in[(cin * 34 + r) * RPITCH];
                const float v0 = src[lane];
                dst[cm0] = make_float2(v0, v0);
                if (lane < 2) {
                    const float v1 = src[32 + lane];
                    dst[40 + lane] = make_float2(v1, v1);   // colmap(32+lane)
                }
            }
        }
    } else {
        #pragma unroll
        for (int cin = 0; cin < 4; cin++) {
            for (int r = wid8; r < 34; r += 8) {
                const int gr = py0 + r;
                const bool rowok = (unsigned)gr < 512u;
                const float* src = xb + ((size_t)cin * 512 + gr) * 512;
                float2* dst = &s_in[(cin * 34 + r) * RPITCH];
                const int gc0 = px0 + lane;
                float v0 = 0.f;
                if (rowok && (unsigned)gc0 < 512u) v0 = src[gc0];
                dst[cm0] = make_float2(v0, v0);
                if (lane < 2) {
                    const int gc1 = px0 + 32 + lane;
                    float v1 = 0.f;
                    if (rowok && (unsigned)gc1 < 512u) v1 = src[gc1];
                    dst[40 + lane] = make_float2(v1, v1);
                }
            }
        }
    }
    __syncthreads();

    const int m   = tid & 3;
    const int tcx = (tid >> 2) & 3;
    const int ty  = tid >> 4;

    const float* s_wm = s_w + m * 8;   // weight base for this thread's m

    // acc[g][sp]: f32x2 = (out j=0, out j=1) for plane co = 2g + (m>>1),
    // out row 2*(h0+ty) + (m&1), superpixel x = w0 + 4*tcx + sp
    unsigned long long acc[4][4];
    #pragma unroll
    for (int g = 0; g < 4; g++)
        #pragma unroll
        for (int sp = 0; sp < 4; sp++)
            acc[g][sp] = 0ull;

    // apply buffered row to group-half gy (g = 2*gy, 2*gy+1) at tap row ky
    #define APPLY(GY, KY, CIN, ROW)                                         \
    {                                                                       \
        _Pragma("unroll")                                                   \
        for (int kx = 0; kx < 3; kx++) {                                    \
            const float* wb = s_wm + ((CIN) * 9 + (KY) * 3 + kx) * 32       \
                              + (GY) * 4;                                   \
            const ulonglong2 wp = *(const ulonglong2*)(wb);                 \
            _Pragma("unroll")                                               \
            for (int sp = 0; sp < 4; sp++) {                                \
                ffma2(acc[2 * (GY) + 0][sp], wp.x, (ROW)[2 * sp + 0 + kx]); \
                ffma2(acc[2 * (GY) + 1][sp], wp.y, (ROW)[2 * sp + 1 + kx]); \
            }                                                               \
        }                                                                   \
    }

    #pragma unroll
    for (int cin = 0; cin < 4; cin++) {
        // base of this thread's 10-position window: group tcx starts at 10*tcx
        const float2* rowbase = &s_in[(cin * 34 + 2 * ty) * RPITCH + 10 * tcx];
        unsigned long long rA[10], rB[10];

        // double-buffered schedule: each ldrow issues one APPLY ahead of use
        ldrow(rA, rowbase);                  // A = r0
        ldrow(rB, rowbase + RPITCH);         // B = r1   (prefetch)
        APPLY(0, 0, cin, rA)                 // consume r0
        ldrow(rA, rowbase + 2 * RPITCH);     // A = r2   (prefetch)
        APPLY(0, 1, cin, rB)                 // consume r1
        APPLY(1, 0, cin, rB)
        ldrow(rB, rowbase + 3 * RPITCH);     // B = r3   (prefetch)
        APPLY(0, 2, cin, rA)                 // consume r2
        APPLY(1, 1, cin, rA)
        APPLY(1, 2, cin, rB)                 // consume r3
    }
    #undef APPLY

    // ---- coalesced stores: per g, 8 consecutive px = 2x STG.128 ----
    float* ob = out + (size_t)b * 8 * 512 * 512;
    const int row_y = 2 * (h0 + ty) + (m & 1);
    const int colbase = 2 * w0 + 8 * tcx;
    #pragma unroll
    for (int g = 0; g < 4; g++) {
        const int co = 2 * g + (m >> 1);
        float* orow = ob + ((size_t)co * 512 + row_y) * 512 + colbase;
        ulonglong2 v0; v0.x = acc[g][0]; v0.y = acc[g][1];
        ulonglong2 v1; v1.x = acc[g][2]; v1.y = acc[g][3];
        *(ulonglong2*)(orow) = v0;
        *(ulonglong2*)(orow + 4) = v1;
    }
}

extern "C" void kernel_launch(void* const* d_in, const int* in_sizes, int n_in,
                              void* d_out, int out_size) {
    const float* x = (const float*)d_in[0];   // [8,4,512,512]
    const float* w = (const float*)d_in[1];   // [32,36,1,1]
    float* out = (float*)d_out;               // [8,8,512,512]
    const int smem_bytes = 4 * 34 * RPITCH * (int)sizeof(float2);  // 47872
    cudaFuncSetAttribute(pconv_kernel,
                         cudaFuncAttributeMaxDynamicSharedMemorySize,
                         smem_bytes);
    dim3 grid(16, 16, 8);                     // 2048 blocks, 256 thr
    pconv_kernel<<<grid, 256, smem_bytes>>>(x, w, out);
}

// round 13
// speedup vs baseline: 1.4991x; 1.0830x over previous
#include <cuda_runtime.h>
#include <cuda_bf16.h>

// PeriodicConvOp == parity-scrambled 3x3 conv.
// x: [8,4,512,512] f32, weight: [32,36] f32, out: [8,8,512,512] f32.
//
// For flat channel n in [0,32): g = n>>3 (gy=g>>1, gx=g&1), o = n&7:
//   conv[n](h,w) = sum_{cin,ky,kx} W[(g*8+o)*36 + cin*9+ky*3+kx]
//                  * x[b,cin, 2h+gy+ky-1, 2w+gx+kx-1]
//   out[b, n>>2, 2h + ((n>>1)&1), 2w + (n&1)] = conv[n](h,w)
//
// Thread map: m = tid&3 (o-pair -> f32x2 lanes), tcx = (tid>>2)&3
// (4 superpixels), ty = tid>>4. Tile 16x16 superpixels, 256 threads.
//
// R13 = R12 conflict-free gapped input layout (column c stored at float2
// index 10*(c>>3)+(c&7), pitch 44; warp LDS.128 address residues cover all
// 32 banks) + single-live-row schedule (20-reg window, as in the measured
// 64-reg R9 build) + occupancy 4 (32 warps/SM on the unconflicted crossbar).

#define RPITCH 44  // row pitch in float2 (8 data + 2 gap per group of 8)

__device__ __forceinline__ void ffma2(unsigned long long& d,
                                      unsigned long long a,
                                      unsigned long long b) {
    asm("fma.rn.f32x2 %0, %1, %2, %0;" : "+l"(d) : "l"(a), "l"(b));
}

// storage float2-offset of column c within a row (gapped layout)
__device__ __forceinline__ int colmap(int c) {
    return 10 * (c >> 3) + (c & 7);
}

// load 10 consecutive positions from gapped layout: positions 0..7 at
// +0..+7, positions 8..9 at +10,+11 (all 16B-aligned LDS.128).
__device__ __forceinline__ void ldrow(unsigned long long* r, const float2* p) {
    const ulonglong2 a = *(const ulonglong2*)(p);
    const ulonglong2 b = *(const ulonglong2*)(p + 2);
    const ulonglong2 c = *(const ulonglong2*)(p + 4);
    const ulonglong2 d = *(const ulonglong2*)(p + 6);
    const ulonglong2 e = *(const ulonglong2*)(p + 10);
    r[0] = a.x; r[1] = a.y; r[2] = b.x; r[3] = b.y; r[4] = c.x;
    r[5] = c.y; r[6] = d.x; r[7] = d.y; r[8] = e.x; r[9] = e.y;
}

__global__ __launch_bounds__(256, 4)
void pconv_kernel(const float* __restrict__ x, const float* __restrict__ wg,
                  float* __restrict__ out) {
    // dynamic: input tile, duplicated {v,v}, gapped conflict-free layout
    extern __shared__ __align__(16) float2 s_in[];   // 4*34*RPITCH = 47872 B
    // weights: s_w[((tap*4 + m)*4 + g)*2 + e] = W[(g*8 + 2m + e)*36 + tap]
    __shared__ __align__(16) float s_w[1152];

    const int tid  = threadIdx.x;
    const int lane = tid & 31;
    const int wid8 = tid >> 5;            // warp id 0..7
    const int b   = blockIdx.z;
    const int h0  = blockIdx.y * 16;      // superpixel row base
    const int w0  = blockIdx.x * 16;      // superpixel col base
    const int py0 = 2 * h0 - 1;           // pixel row of tile row 0
    const int px0 = 2 * w0 - 1;

    // ---- stage weights (transposed/interleaved) ----
    for (int d = tid; d < 1152; d += 256) {
        int e = d & 1, g = (d >> 1) & 3, m = (d >> 3) & 3, tap = d >> 5;
        s_w[d] = wg[(g * 8 + 2 * m + e) * 36 + tap];
    }

    // ---- stage input tile (duplicated, gapped layout), warp-per-row ----
    const float* xb = x + (size_t)b * 4 * 512 * 512;
    const int cm0 = colmap(lane);         // storage offset of column=lane
    const bool interior = (blockIdx.x > 0) & (blockIdx.x < 15) &
                          (blockIdx.y > 0) & (blockIdx.y < 15);
    if (interior) {
        #pragma unroll
        for (int cin = 0; cin < 4; cin++) {
            for (int r = wid8; r < 34; r += 8) {
                const float* src = xb + ((size_t)cin * 512 + (py0 + r)) * 512
                                   + px0;
                float2* dst = &s_in[(cin * 34 + r) * RPITCH];
                const float v0 = src[lane];
                dst[cm0] = make_float2(v0, v0);
                if (lane < 2) {
                    const float v1 = src[32 + lane];
                    dst[40 + lane] = make_float2(v1, v1);   // colmap(32+lane)
                }
            }
        }
    } else {
        #pragma unroll
        for (int cin = 0; cin < 4; cin++) {
            for (int r = wid8; r < 34; r += 8) {
                const int gr = py0 + r;
                const bool rowok = (unsigned)gr < 512u;
                const float* src = xb + ((size_t)cin * 512 + gr) * 512;
                float2* dst = &s_in[(cin * 34 + r) * RPITCH];
                const int gc0 = px0 + lane;
                float v0 = 0.f;
                if (rowok && (unsigned)gc0 < 512u) v0 = src[gc0];
                dst[cm0] = make_float2(v0, v0);
                if (lane < 2) {
                    const int gc1 = px0 + 32 + lane;
                    float v1 = 0.f;
                    if (rowok && (unsigned)gc1 < 512u) v1 = src[gc1];
                    dst[40 + lane] = make_float2(v1, v1);
                }
            }
        }
    }
    __syncthreads();

    const int m   = tid & 3;
    const int tcx = (tid >> 2) & 3;
    const int ty  = tid >> 4;

    const float* s_wm = s_w + m * 8;   // weight base for this thread's m

    // acc[g][sp]: f32x2 = (out j=0, out j=1) for plane co = 2g + (m>>1),
    // out row 2*(h0+ty) + (m&1), superpixel x = w0 + 4*tcx + sp
    unsigned long long acc[4][4];
    #pragma unroll
    for (int g = 0; g < 4; g++)
        #pragma unroll
        for (int sp = 0; sp < 4; sp++)
            acc[g][sp] = 0ull;

    // apply row to group-half gy (g = 2*gy, 2*gy+1) at tap row ky
    #define APPLY(GY, KY, CIN, ROW)                                         \
    {                                                                       \
        _Pragma("unroll")                                                   \
        for (int kx = 0; kx < 3; kx++) {                                    \
            const float* wb = s_wm + ((CIN) * 9 + (KY) * 3 + kx) * 32       \
                              + (GY) * 4;                                   \
            const ulonglong2 wp = *(const ulonglong2*)(wb);                 \
            _Pragma("unroll")                                               \
            for (int sp = 0; sp < 4; sp++) {                                \
                ffma2(acc[2 * (GY) + 0][sp], wp.x, (ROW)[2 * sp + 0 + kx]); \
                ffma2(acc[2 * (GY) + 1][sp], wp.y, (ROW)[2 * sp + 1 + kx]); \
            }                                                               \
        }                                                                   \
    }

    #pragma unroll
    for (int cin = 0; cin < 4; cin++) {
        // base of this thread's 10-position window: group tcx starts at 10*tcx
        const float2* rowbase = &s_in[(cin * 34 + 2 * ty) * RPITCH + 10 * tcx];
        unsigned long long row[10];

        // single-live-row schedule (fits 64 regs for occupancy 4)
        ldrow(row, rowbase);                 // r = 0
        APPLY(0, 0, cin, row)                //   gy=0, ky=0
        ldrow(row, rowbase + RPITCH);        // r = 1
        APPLY(0, 1, cin, row)                //   gy=0, ky=1
        APPLY(1, 0, cin, row)                //   gy=1, ky=0
        ldrow(row, rowbase + 2 * RPITCH);    // r = 2
        APPLY(0, 2, cin, row)                //   gy=0, ky=2
        APPLY(1, 1, cin, row)                //   gy=1, ky=1
        ldrow(row, rowbase + 3 * RPITCH);    // r = 3
        APPLY(1, 2, cin, row)                //   gy=1, ky=2
    }
    #undef APPLY

    // ---- coalesced stores: per g, 8 consecutive px = 2x STG.128 ----
    float* ob = out + (size_t)b * 8 * 512 * 512;
    const int row_y = 2 * (h0 + ty) + (m & 1);
    const int colbase = 2 * w0 + 8 * tcx;
    #pragma unroll
    for (int g = 0; g < 4; g++) {
        const int co = 2 * g + (m >> 1);
        float* orow = ob + ((size_t)co * 512 + row_y) * 512 + colbase;
        ulonglong2 v0; v0.x = acc[g][0]; v0.y = acc[g][1];
        ulonglong2 v1; v1.x = acc[g][2]; v1.y = acc[g][3];
        *(ulonglong2*)(orow) = v0;
        *(ulonglong2*)(orow + 4) = v1;
    }
}

extern "C" void kernel_launch(void* const* d_in, const int* in_sizes, int n_in,
                              void* d_out, int out_size) {
    const float* x = (const float*)d_in[0];   // [8,4,512,512]
    const float* w = (const float*)d_in[1];   // [32,36,1,1]
    float* out = (float*)d_out;               // [8,8,512,512]
    const int smem_bytes = 4 * 34 * RPITCH * (int)sizeof(float2);  // 47872
    cudaFuncSetAttribute(pconv_kernel,
                         cudaFuncAttributeMaxDynamicSharedMemorySize,
                         smem_bytes);
    dim3 grid(16, 16, 8);                     // 2048 blocks, 256 thr
    pconv_kernel<<<grid, 256, smem_bytes>>>(x, w, out);
}